// round 2
// baseline (speedup 1.0000x reference)
#include <cuda_runtime.h>

// RandFlow blur: depthwise 41x41 Gaussian (sigma=5) on flow = 2*noise - 1.
// Separable: two 1D 41-tap passes. Normalization 1/S^2 and the affine
// (2x-1) are folded into the pass-1 load so both passes use the raw
// (unnormalized) Gaussian taps as COMPILE-TIME LITERALS -> FFMA-imm (rt=1).

#define IMG_H 512
#define IMG_W 512
#define IMG_B 16
#define NROWS (IMG_B * IMG_H)

// Intermediate (pass1 horizontal result), 33.5 MB -> fits in L2 (126 MB).
__device__ float2 g_scratch[IMG_B * IMG_H * IMG_W];

// Raw taps g(d) = exp(-d^2/50), d = |k-20|, k = 0..40 (unnormalized).
__device__ constexpr float GK[41] = {
    0.00033546f, 0.00073182f, 0.00153381f, 0.00308872f, 0.00597603f,
    0.01110900f, 0.01984110f, 0.03404746f, 0.05613476f, 0.08892166f,
    0.13533528f, 0.19789871f, 0.27803730f, 0.37531110f, 0.48675226f,
    0.60653066f, 0.72614904f, 0.83527021f, 0.92311635f, 0.98019867f,
    1.00000000f,
    0.98019867f, 0.92311635f, 0.83527021f, 0.72614904f, 0.60653066f,
    0.48675226f, 0.37531110f, 0.27803730f, 0.19789871f, 0.13533528f,
    0.08892166f, 0.05613476f, 0.03404746f, 0.01984110f, 0.01110900f,
    0.00597603f, 0.00308872f, 0.00153381f, 0.00073182f, 0.00033546f
};

// S = sum(g) = 12.5326388 ; fold 1/S^2 and (2x-1) into the load:
// v = x * (2/S^2) + (-1/S^2)
#define SCALE_A 0.012733434f
#define SCALE_B (-0.006366717f)

// ---------------- Pass 1: horizontal 41-tap, fused flow transform ----------
// One block per image row (8192 blocks, 128 threads, 4 outputs/thread).
__global__ void __launch_bounds__(128) rf_pass1(const float2* __restrict__ in) {
    __shared__ float2 s[IMG_W + 40];
    const int row = blockIdx.x;                  // b*512 + h
    const float2* src = in + row * IMG_W;

    for (int i = threadIdx.x; i < IMG_W + 40; i += 128) {
        int w = i - 20;
        float2 v = make_float2(0.f, 0.f);
        if ((unsigned)w < (unsigned)IMG_W) {
            float2 t = src[w];
            v.x = fmaf(t.x, SCALE_A, SCALE_B);
            v.y = fmaf(t.y, SCALE_A, SCALE_B);
        }
        s[i] = v;
    }
    __syncthreads();

    const int base = threadIdx.x * 4;
    float2 acc[4] = {};
#pragma unroll
    for (int t = 0; t < 44; ++t) {
        float2 v = s[base + t];
#pragma unroll
        for (int r = 0; r < 4; ++r) {
            const int k = t - r;
            if (k >= 0 && k < 41) {
                acc[r].x = fmaf(v.x, GK[k], acc[r].x);
                acc[r].y = fmaf(v.y, GK[k], acc[r].y);
            }
        }
    }
    float4* dst = reinterpret_cast<float4*>(g_scratch + row * IMG_W + base);
    dst[0] = make_float4(acc[0].x, acc[0].y, acc[1].x, acc[1].y);
    dst[1] = make_float4(acc[2].x, acc[2].y, acc[3].x, acc[3].y);
}

// ---------------- Pass 2: vertical 41-tap --------------------------------
// 16 outputs per thread (register-blocked), coalesced float2 loads from the
// L2-resident scratch. grid = 16 batches * 32 h-blocks * 4 w-blocks = 2048.
#define R2 16
__global__ void __launch_bounds__(128) rf_pass2(float2* __restrict__ out) {
    const int w  = (blockIdx.x & 3) * 128 + threadIdx.x;
    const int bh = blockIdx.x >> 2;           // 0 .. 16*32-1
    const int b  = bh >> 5;
    const int h0 = (bh & 31) * R2;

    const float2* src = g_scratch + (size_t)b * IMG_H * IMG_W + w;
    float2 acc[R2] = {};

#pragma unroll
    for (int t = 0; t < R2 + 40; ++t) {
        const int h = h0 + t - 20;
        float2 v = make_float2(0.f, 0.f);
        if ((unsigned)h < (unsigned)IMG_H) v = src[(size_t)h * IMG_W];
#pragma unroll
        for (int r = 0; r < R2; ++r) {
            const int k = t - r;
            if (k >= 0 && k < 41) {
                acc[r].x = fmaf(v.x, GK[k], acc[r].x);
                acc[r].y = fmaf(v.y, GK[k], acc[r].y);
            }
        }
    }

    float2* dst = out + ((size_t)b * IMG_H + h0) * IMG_W + w;
#pragma unroll
    for (int r = 0; r < R2; ++r) dst[(size_t)r * IMG_W] = acc[r];
}

extern "C" void kernel_launch(void* const* d_in, const int* in_sizes, int n_in,
                              void* d_out, int out_size) {
    // Select rand_noise robustly by element count (16*512*512*2).
    const float2* noise = nullptr;
    for (int i = 0; i < n_in; ++i) {
        if (in_sizes[i] == IMG_B * IMG_H * IMG_W * 2) {
            noise = (const float2*)d_in[i];
            break;
        }
    }
    if (!noise) noise = (const float2*)d_in[n_in - 1];

    float2* out = (float2*)d_out;
    rf_pass1<<<NROWS, 128>>>(noise);
    rf_pass2<<<IMG_B * (IMG_H / R2) * (IMG_W / 128), 128>>>(out);
}

// round 3
// speedup vs baseline: 1.0094x; 1.0094x over previous
#include <cuda_runtime.h>

// RandFlow: depthwise 41x41 Gaussian (sigma=5) of flow = 2*noise-1, separable.
// Both passes: tap-outer sliding-window, 16 outputs/thread, packed fma.rn.f32x2
// (both flow channels per instruction). Taps are compile-time literals.

#define IMG_H 512
#define IMG_W 512
#define IMG_B 16

__device__ unsigned long long g_scratch[IMG_B * IMG_H * IMG_W]; // float2 as u64

__device__ constexpr float GK[41] = {
    0.00033546f, 0.00073182f, 0.00153381f, 0.00308872f, 0.00597603f,
    0.01110900f, 0.01984110f, 0.03404746f, 0.05613476f, 0.08892166f,
    0.13533528f, 0.19789871f, 0.27803730f, 0.37531110f, 0.48675226f,
    0.60653066f, 0.72614904f, 0.83527021f, 0.92311635f, 0.98019867f,
    1.00000000f,
    0.98019867f, 0.92311635f, 0.83527021f, 0.72614904f, 0.60653066f,
    0.48675226f, 0.37531110f, 0.27803730f, 0.19789871f, 0.13533528f,
    0.08892166f, 0.05613476f, 0.03404746f, 0.01984110f, 0.01110900f,
    0.00597603f, 0.00308872f, 0.00153381f, 0.00073182f, 0.00033546f
};

// fold 1/S^2 (S = 12.5326388) and (2x-1) into pass-1 load
#define SCALE_A 0.012733434f
#define SCALE_B (-0.006366717f)

__device__ __forceinline__ unsigned long long pk2(float g) {
    unsigned int u = __float_as_uint(g);           // constant-folds for literals
    return ((unsigned long long)u << 32) | (unsigned long long)u;
}
__device__ __forceinline__ void ffma2(unsigned long long& d,
                                      unsigned long long a,
                                      unsigned long long b) {
    asm("fma.rn.f32x2 %0, %1, %2, %0;" : "+l"(d) : "l"(a), "l"(b));
}

// ---------------- Pass 1: horizontal, smem row cache (skewed) --------------
// 1 warp per row, 4 rows per block. Thread: 16 consecutive w-outputs.
__global__ void __launch_bounds__(128) rf_pass1(const float2* __restrict__ in) {
    __shared__ unsigned long long s[4][592];   // 552 + skew(34) per row
    const int warp = threadIdx.x >> 5;
    const int lane = threadIdx.x & 31;
    const int row  = blockIdx.x * 4 + warp;    // b*512 + h
    const float2* src = in + (size_t)row * IMG_W;
    unsigned long long* S = s[warp];

    // fill padded row: x in [0,552), input w = x-20, affine folded in
    for (int x = lane; x < IMG_W + 40; x += 32) {
        float vx = 0.f, vy = 0.f;
        int w = x - 20;
        if ((unsigned)w < (unsigned)IMG_W) {
            float2 t = src[w];
            vx = fmaf(t.x, SCALE_A, SCALE_B);
            vy = fmaf(t.y, SCALE_A, SCALE_B);
        }
        S[x + (x >> 4)] = ((unsigned long long)__float_as_uint(vy) << 32)
                        |  (unsigned long long)__float_as_uint(vx);
    }
    __syncwarp();

    const int base = lane * 17;                // skewed base of lane's window
    unsigned long long win[16], acc[16];
#pragma unroll
    for (int i = 0; i < 16; ++i) { win[i] = S[base + i]; acc[i] = 0ull; }

#pragma unroll
    for (int k = 0; k < 41; ++k) {
        const unsigned long long g = pk2(GK[k]);
#pragma unroll
        for (int r = 0; r < 16; ++r) ffma2(acc[r], win[(k + r) & 15], g);
        if (k < 40) {
            const int c = k + 16;
            win[k & 15] = S[base + c + (c >> 4)];
        }
    }
    __syncwarp();

    // stage outputs to smem (skewed: idx = 17*lane + r), then coalesced store
#pragma unroll
    for (int r = 0; r < 16; ++r) S[base + r] = acc[r];
    __syncwarp();

    unsigned long long* dst = g_scratch + (size_t)row * IMG_W;
#pragma unroll
    for (int j = 0; j < 16; ++j) {
        const int x = lane + 32 * j;
        dst[x] = S[x + (x >> 4)];
    }
}

// ---------------- Pass 2: vertical, 20-deep register window ---------------
// 128 threads = 128 consecutive w; thread does 16 consecutive h-outputs.
#define W2 20
__global__ void __launch_bounds__(128) rf_pass2(float2* __restrict__ out) {
    const int w  = (blockIdx.x & 3) * 128 + threadIdx.x;
    const int bh = blockIdx.x >> 2;
    const int b  = bh >> 5;
    const int h0 = (bh & 31) * 16;

    const unsigned long long* src =
        g_scratch + (size_t)b * IMG_H * IMG_W + w;

    unsigned long long win[W2], acc[16];
#pragma unroll
    for (int j = 0; j < W2; ++j) {
        const int h = h0 + j - 20;
        win[j] = ((unsigned)h < (unsigned)IMG_H) ? src[(size_t)h * IMG_W] : 0ull;
    }
#pragma unroll
    for (int r = 0; r < 16; ++r) acc[r] = 0ull;

#pragma unroll
    for (int k = 0; k < 41; ++k) {
        const unsigned long long g = pk2(GK[k]);
#pragma unroll
        for (int r = 0; r < 16; ++r) ffma2(acc[r], win[(k + r) % W2], g);
        const int h = h0 + k;                  // prefetch j = k + 20
        win[k % W2] = ((unsigned)h < (unsigned)IMG_H) ? src[(size_t)h * IMG_W] : 0ull;
    }

    unsigned long long* dst = (unsigned long long*)out
                            + ((size_t)b * IMG_H + h0) * IMG_W + w;
#pragma unroll
    for (int r = 0; r < 16; ++r) dst[(size_t)r * IMG_W] = acc[r];
}

extern "C" void kernel_launch(void* const* d_in, const int* in_sizes, int n_in,
                              void* d_out, int out_size) {
    const float2* noise = nullptr;
    for (int i = 0; i < n_in; ++i) {
        if (in_sizes[i] == IMG_B * IMG_H * IMG_W * 2) {
            noise = (const float2*)d_in[i];
            break;
        }
    }
    if (!noise) noise = (const float2*)d_in[n_in - 1];

    rf_pass1<<<IMG_B * IMG_H / 4, 128>>>(noise);
    rf_pass2<<<IMG_B * (IMG_H / 16) * (IMG_W / 128), 128>>>((float2*)d_out);
}